// round 4
// baseline (speedup 1.0000x reference)
#include <cuda_runtime.h>

// Fixed problem shape: B=1, T=4, V=6, H=128, W=128
#define MAXID    8192
#define BT       4
#define M_ELEMS  393216
#define VHW      (M_ELEMS / BT)       // 98304
#define NSEGS    (BT * MAXID)         // 32768
#define REC      112                  // per-segment record (floats), 448B
#define THRF     2.0f
#define DUPF     0.05f
#define FULL     0xffffffffu

// Record layout (float slots):
//  [0..63] dense  [64..79] inst  [80..87] motion  [88..91] rot
//  [92..94] center [95..97] offset [98] opacity [99..101] scale
//  [102..104] feat_dc [105] dyn [106] d2 (sum e2) [107..111] pad

__device__ int                g_cnt[NSEGS];
__device__ float4             g_e1c[NSEGS];   // {d1, sum(cen*e1).xyz}
__device__ unsigned long long g_rep[NSEGS];   // packed (ordered(k)<<32 | ~i)
__device__ unsigned char      g_act[M_ELEMS];
__device__ __align__(16) float g_sums[(size_t)NSEGS * REC];

__device__ __forceinline__ void red4(float* addr, float a, float b, float c, float d) {
    asm volatile("red.global.add.v4.f32 [%0], {%1,%2,%3,%4};"
                 :: "l"(addr), "f"(a), "f"(b), "f"(c), "f"(d) : "memory");
}

// ---------------- Pass 1: count + e1/cen*e1 accumulate (4 elems/thread) ----
__global__ void k_p12(const int* __restrict__ ids, const float* __restrict__ kp,
                      const float* __restrict__ cen) {
    int base = (blockIdx.x * blockDim.x + threadIdx.x) * 4;
    if (base >= M_ELEMS) return;
    int4   id4 = *(const int4*)(ids + base);
    float4 k4  = *(const float4*)(kp + base);
    float4 c0 = *(const float4*)(cen + (size_t)base * 3);
    float4 c1 = *(const float4*)(cen + (size_t)base * 3 + 4);
    float4 c2 = *(const float4*)(cen + (size_t)base * 3 + 8);
    int bt = base / VHW;   // VHW % 4 == 0, no straddle

    int   idv[4] = {id4.x, id4.y, id4.z, id4.w};
    float kv[4]  = {k4.x, k4.y, k4.z, k4.w};
    float cx[4] = {c0.x, c0.w, c1.z, c2.y};
    float cy[4] = {c0.y, c1.x, c1.w, c2.z};
    float cz[4] = {c0.z, c1.y, c2.x, c2.w};
#pragma unroll
    for (int j = 0; j < 4; j++) {
        if (idv[j] >= 0) {
            int seg = bt * MAXID + idv[j];
            float e1 = expf(kv[j]);
            atomicAdd(&g_cnt[seg], 1);
            red4((float*)&g_e1c[seg], e1, cx[j] * e1, cy[j] * e1, cz[j] * e1);
        }
    }
}

// ------- Pass 2 (fused p3+p4): act + packed rep + weighted accumulate ------
__global__ void k_p34(const float* __restrict__ dense, const float* __restrict__ cen,
                      const float* __restrict__ off,   const float* __restrict__ opa,
                      const float* __restrict__ sca,   const float* __restrict__ rot,
                      const float* __restrict__ fdc,   const float* __restrict__ kp,
                      const float* __restrict__ inst,  const float* __restrict__ mot,
                      const float* __restrict__ dyn,   const int* __restrict__ ids) {
    int i = blockIdx.x * blockDim.x + threadIdx.x;
    if (i >= M_ELEMS) return;

    int id = ids[i];
    unsigned char act = 0;
    int seg = 0;
    float k0 = 0.f;
    if (id >= 0) {
        seg = (i / VHW) * MAXID + id;
        if (__ldg(&g_cnt[seg]) >= 2) {
            float4 f = __ldg(&g_e1c[seg]);
            float inv = (f.x > 0.0f) ? (1.0f / f.x) : 1.0f;
            float dx = cen[3 * (size_t)i + 0] - f.y * inv;
            float dy = cen[3 * (size_t)i + 1] - f.z * inv;
            float dz = cen[3 * (size_t)i + 2] - f.w * inv;
            float dist = sqrtf(dx * dx + dy * dy + dz * dz);
            if (dist <= THRF) { act = 1; k0 = kp[i]; }
        }
    }
    g_act[i] = act;
    if (!act) return;

    // representative: max keep_score, tie -> min index (packed 64-bit max)
    unsigned kb  = __float_as_uint(k0);
    unsigned ord = (k0 >= 0.0f) ? (kb | 0x80000000u) : ~kb;
    atomicMax(&g_rep[seg], ((unsigned long long)ord << 32) | (FULL - (unsigned)i));

    float e2 = expf(k0);
    float* base = g_sums + (size_t)seg * REC;

    const float4* dv = (const float4*)(dense + (size_t)i * 64);
#pragma unroll
    for (int k = 0; k < 16; k++) {
        float4 v = dv[k];
        red4(base + 4 * k, v.x * e2, v.y * e2, v.z * e2, v.w * e2);
    }
    const float4* iv = (const float4*)(inst + (size_t)i * 16);
#pragma unroll
    for (int k = 0; k < 4; k++) {
        float4 v = iv[k];
        red4(base + 64 + 4 * k, v.x * e2, v.y * e2, v.z * e2, v.w * e2);
    }
    const float4* mv = (const float4*)(mot + (size_t)i * 8);
#pragma unroll
    for (int k = 0; k < 2; k++) {
        float4 v = mv[k];
        red4(base + 80 + 4 * k, v.x * e2, v.y * e2, v.z * e2, v.w * e2);
    }
    {
        float4 v = ((const float4*)(rot + (size_t)i * 4))[0];
        red4(base + 88, v.x * e2, v.y * e2, v.z * e2, v.w * e2);
    }
    float c0 = cen[3 * (size_t)i], c1 = cen[3 * (size_t)i + 1], c2 = cen[3 * (size_t)i + 2];
    float o0 = off[3 * (size_t)i], o1 = off[3 * (size_t)i + 1], o2 = off[3 * (size_t)i + 2];
    float op = opa[i];
    float s0 = sca[3 * (size_t)i], s1 = sca[3 * (size_t)i + 1], s2 = sca[3 * (size_t)i + 2];
    float f0 = fdc[3 * (size_t)i], f1 = fdc[3 * (size_t)i + 1], f2 = fdc[3 * (size_t)i + 2];
    float dn = dyn[i];
    red4(base + 92,  c0 * e2, c1 * e2, c2 * e2, o0 * e2);
    red4(base + 96,  o1 * e2, o2 * e2, op * e2, s0 * e2);
    red4(base + 100, s1 * e2, s2 * e2, f0 * e2, f1 * e2);
    red4(base + 104, f2 * e2, dn * e2, e2,      0.0f);
}

// ---------------- Pass 3: warp-per-element output scatter ----------------
__global__ void k_out(const float* __restrict__ dense, const float* __restrict__ cen,
                      const float* __restrict__ off,   const float* __restrict__ opa,
                      const float* __restrict__ sca,   const float* __restrict__ rot,
                      const float* __restrict__ fdc,   const float* __restrict__ kp,
                      const float* __restrict__ inst,  const float* __restrict__ mot,
                      const float* __restrict__ dyn,   const int* __restrict__ ids,
                      float* __restrict__ out) {
    int i = (blockIdx.x * blockDim.x + threadIdx.x) >> 5;
    int l = threadIdx.x & 31;
    if (i >= M_ELEMS) return;

    const size_t M = M_ELEMS;
    float* o_dense = out;
    float* o_cen   = out + 64 * M;
    float* o_off   = out + 67 * M;
    float* o_opa   = out + 70 * M;
    float* o_sca   = out + 71 * M;
    float* o_rot   = out + 74 * M;
    float* o_fdc   = out + 78 * M;
    float* o_kp    = out + 81 * M;
    float* o_inst  = out + 82 * M;
    float* o_mot   = out + 98 * M;
    float* o_dyn   = out + 106 * M;

    if (__ldg(&g_act[i])) {
        int seg = (i / VHW) * MAXID + __ldg(&ids[i]);
        const float* r = g_sums + (size_t)seg * REC;
        float inv = 1.0f / __ldg(r + 106);            // d2 > 0 for active
        unsigned long long pk = __ldg(&g_rep[seg]);
        unsigned rep_i = FULL - (unsigned)(pk & FULL);
        unsigned ou = (unsigned)(pk >> 32);
        float mx2 = (ou & 0x80000000u) ? __uint_as_float(ou & 0x7FFFFFFFu)
                                       : __uint_as_float(~ou);
        float fac = ((unsigned)i == rep_i) ? 1.0f : DUPF;

        if (l < 27) {
            float4 v = __ldg((const float4*)r + l);
            v.x *= inv; v.y *= inv; v.z *= inv; v.w *= inv;
            if (l < 16) {
                ((float4*)(o_dense + (size_t)i * 64))[l] = v;
            } else if (l < 20) {
                ((float4*)(o_inst + (size_t)i * 16))[l - 16] = v;
            } else if (l < 22) {
                ((float4*)(o_mot + (size_t)i * 8))[l - 20] = v;
            } else if (l == 22) {
                float n = sqrtf(v.x * v.x + v.y * v.y + v.z * v.z + v.w * v.w);
                float qi = 1.0f / fmaxf(n, 1e-12f);
                ((float4*)(o_rot + (size_t)i * 4))[0] =
                    make_float4(v.x * qi, v.y * qi, v.z * qi, v.w * qi);
            } else if (l == 23) {          // rec[92..95]: cen xyz, off0
                o_cen[3 * (size_t)i + 0] = v.x;
                o_cen[3 * (size_t)i + 1] = v.y;
                o_cen[3 * (size_t)i + 2] = v.z;
                o_off[3 * (size_t)i + 0] = v.w;
            } else if (l == 24) {          // rec[96..99]: off1 off2 opa sca0
                o_off[3 * (size_t)i + 1] = v.x;
                o_off[3 * (size_t)i + 2] = v.y;
                o_opa[i] = v.z * fac;
                o_sca[3 * (size_t)i + 0] = v.w;
            } else if (l == 25) {          // rec[100..103]: sca1 sca2 fdc0 fdc1
                o_sca[3 * (size_t)i + 1] = v.x;
                o_sca[3 * (size_t)i + 2] = v.y;
                o_fdc[3 * (size_t)i + 0] = v.z;
                o_fdc[3 * (size_t)i + 1] = v.w;
            } else {                       // l==26, rec[104..107]: fdc2 dyn d2 pad
                o_fdc[3 * (size_t)i + 2] = v.x;
                o_dyn[i] = v.y;
            }
        } else if (l == 27) {
            o_kp[i] = mx2 * fac;
        }
    } else {
        if (l < 16) {
            ((float4*)(o_dense + (size_t)i * 64))[l] =
                __ldg((const float4*)(dense + (size_t)i * 64) + l);
        } else if (l < 20) {
            ((float4*)(o_inst + (size_t)i * 16))[l - 16] =
                __ldg((const float4*)(inst + (size_t)i * 16) + (l - 16));
        } else if (l < 22) {
            ((float4*)(o_mot + (size_t)i * 8))[l - 20] =
                __ldg((const float4*)(mot + (size_t)i * 8) + (l - 20));
        } else if (l == 22) {
            ((float4*)(o_rot + (size_t)i * 4))[0] =
                __ldg((const float4*)(rot + (size_t)i * 4));
        } else if (l == 23) {
            o_cen[3 * (size_t)i + 0] = __ldg(cen + 3 * (size_t)i + 0);
            o_cen[3 * (size_t)i + 1] = __ldg(cen + 3 * (size_t)i + 1);
            o_cen[3 * (size_t)i + 2] = __ldg(cen + 3 * (size_t)i + 2);
        } else if (l == 24) {
            o_off[3 * (size_t)i + 0] = __ldg(off + 3 * (size_t)i + 0);
            o_off[3 * (size_t)i + 1] = __ldg(off + 3 * (size_t)i + 1);
            o_off[3 * (size_t)i + 2] = __ldg(off + 3 * (size_t)i + 2);
        } else if (l == 25) {
            o_sca[3 * (size_t)i + 0] = __ldg(sca + 3 * (size_t)i + 0);
            o_sca[3 * (size_t)i + 1] = __ldg(sca + 3 * (size_t)i + 1);
            o_sca[3 * (size_t)i + 2] = __ldg(sca + 3 * (size_t)i + 2);
        } else if (l == 26) {
            o_fdc[3 * (size_t)i + 0] = __ldg(fdc + 3 * (size_t)i + 0);
            o_fdc[3 * (size_t)i + 1] = __ldg(fdc + 3 * (size_t)i + 1);
            o_fdc[3 * (size_t)i + 2] = __ldg(fdc + 3 * (size_t)i + 2);
        } else if (l == 27) {
            o_opa[i] = __ldg(opa + i);
            o_kp[i]  = __ldg(kp + i);
            o_dyn[i] = __ldg(dyn + i);
        }
    }
}

extern "C" void kernel_launch(void* const* d_in, const int* in_sizes, int n_in,
                              void* d_out, int out_size) {
    const float* dense = (const float*)d_in[0];
    const float* cen   = (const float*)d_in[1];
    const float* off   = (const float*)d_in[2];
    const float* opa   = (const float*)d_in[3];
    const float* sca   = (const float*)d_in[4];
    const float* rot   = (const float*)d_in[5];
    const float* fdc   = (const float*)d_in[6];
    const float* kp    = (const float*)d_in[7];
    const float* inst  = (const float*)d_in[8];
    const float* mot   = (const float*)d_in[9];
    const float* dyn   = (const float*)d_in[10];
    const int*   ids   = (const int*)d_in[11];
    float* out = (float*)d_out;

    // zero scratch via DMA memsets (all-zero patterns are valid initials)
    void *p_cnt, *p_e1c, *p_rep, *p_sums;
    cudaGetSymbolAddress(&p_cnt,  g_cnt);
    cudaGetSymbolAddress(&p_e1c,  g_e1c);
    cudaGetSymbolAddress(&p_rep,  g_rep);
    cudaGetSymbolAddress(&p_sums, g_sums);
    cudaMemsetAsync(p_cnt,  0, sizeof(int) * NSEGS);
    cudaMemsetAsync(p_e1c,  0, sizeof(float4) * NSEGS);
    cudaMemsetAsync(p_rep,  0, sizeof(unsigned long long) * NSEGS);
    cudaMemsetAsync(p_sums, 0, sizeof(float) * (size_t)NSEGS * REC);

    const int TB = 256;
    const int gM = (M_ELEMS + TB - 1) / TB;
    const int g4 = (M_ELEMS / 4 + TB - 1) / TB;
    const int gW = (int)(((long long)M_ELEMS * 32 + TB - 1) / TB);

    k_p12<<<g4, TB>>>(ids, kp, cen);
    k_p34<<<gM, TB>>>(dense, cen, off, opa, sca, rot, fdc, kp, inst, mot, dyn, ids);
    k_out<<<gW, TB>>>(dense, cen, off, opa, sca, rot, fdc, kp, inst, mot, dyn, ids, out);
}

// round 5
// speedup vs baseline: 1.6611x; 1.6611x over previous
#include <cuda_runtime.h>

// Fixed problem shape: B=1, T=4, V=6, H=128, W=128
#define MAXID    8192
#define BT       4
#define M_ELEMS  393216
#define VHW      (M_ELEMS / BT)       // 98304
#define NSEGS    (BT * MAXID)         // 32768
#define REC      112                  // per-segment record (floats), 448B
#define THRF     2.0f
#define DUPF     0.05f
#define FULL     0xffffffffu
#define NE       64                   // elements per k_out block

// Record layout (float slots):
//  [0..63] dense  [64..79] inst  [80..87] motion  [88..91] rot
//  [92..94] center [95..97] offset [98] opacity [99..101] scale
//  [102..104] feat_dc [105] dyn [106] d2 (sum e2) [107..111] pad

__device__ int                g_cnt[NSEGS];
__device__ float4             g_e1c[NSEGS];   // {d1, sum(cen*e1).xyz}
__device__ unsigned long long g_rep[NSEGS];   // packed (ordered(k)<<32 | ~i)
__device__ unsigned char      g_act[M_ELEMS];
__device__ __align__(16) float g_sums[(size_t)NSEGS * REC];

__device__ __forceinline__ void red4(float* addr, float a, float b, float c, float d) {
    asm volatile("red.global.add.v4.f32 [%0], {%1,%2,%3,%4};"
                 :: "l"(addr), "f"(a), "f"(b), "f"(c), "f"(d) : "memory");
}

// ---------------- Pass 1: count + e1/cen*e1 accumulate (4 elems/thread) ----
__global__ void k_p12(const int* __restrict__ ids, const float* __restrict__ kp,
                      const float* __restrict__ cen) {
    int base = (blockIdx.x * blockDim.x + threadIdx.x) * 4;
    if (base >= M_ELEMS) return;
    int4   id4 = *(const int4*)(ids + base);
    float4 k4  = *(const float4*)(kp + base);
    float4 c0 = *(const float4*)(cen + (size_t)base * 3);
    float4 c1 = *(const float4*)(cen + (size_t)base * 3 + 4);
    float4 c2 = *(const float4*)(cen + (size_t)base * 3 + 8);
    int bt = base / VHW;   // VHW % 4 == 0, no straddle

    int   idv[4] = {id4.x, id4.y, id4.z, id4.w};
    float kv[4]  = {k4.x, k4.y, k4.z, k4.w};
    float cx[4] = {c0.x, c0.w, c1.z, c2.y};
    float cy[4] = {c0.y, c1.x, c1.w, c2.z};
    float cz[4] = {c0.z, c1.y, c2.x, c2.w};
#pragma unroll
    for (int j = 0; j < 4; j++) {
        if (idv[j] >= 0) {
            int seg = bt * MAXID + idv[j];
            float e1 = expf(kv[j]);
            atomicAdd(&g_cnt[seg], 1);
            red4((float*)&g_e1c[seg], e1, cx[j] * e1, cy[j] * e1, cz[j] * e1);
        }
    }
}

// ------- Pass 2 (fused): act + packed rep + weighted accumulate ------
__global__ void k_p34(const float* __restrict__ dense, const float* __restrict__ cen,
                      const float* __restrict__ off,   const float* __restrict__ opa,
                      const float* __restrict__ sca,   const float* __restrict__ rot,
                      const float* __restrict__ fdc,   const float* __restrict__ kp,
                      const float* __restrict__ inst,  const float* __restrict__ mot,
                      const float* __restrict__ dyn,   const int* __restrict__ ids) {
    int i = blockIdx.x * blockDim.x + threadIdx.x;
    if (i >= M_ELEMS) return;

    int id = ids[i];
    unsigned char act = 0;
    int seg = 0;
    float k0 = 0.f;
    if (id >= 0) {
        seg = (i / VHW) * MAXID + id;
        if (__ldg(&g_cnt[seg]) >= 2) {
            float4 f = __ldg(&g_e1c[seg]);
            float inv = (f.x > 0.0f) ? (1.0f / f.x) : 1.0f;
            float dx = cen[3 * (size_t)i + 0] - f.y * inv;
            float dy = cen[3 * (size_t)i + 1] - f.z * inv;
            float dz = cen[3 * (size_t)i + 2] - f.w * inv;
            float dist = sqrtf(dx * dx + dy * dy + dz * dz);
            if (dist <= THRF) { act = 1; k0 = kp[i]; }
        }
    }
    g_act[i] = act;
    if (!act) return;

    // representative: max keep_score, tie -> min index (packed 64-bit max)
    unsigned kb  = __float_as_uint(k0);
    unsigned ord = (k0 >= 0.0f) ? (kb | 0x80000000u) : ~kb;
    atomicMax(&g_rep[seg], ((unsigned long long)ord << 32) | (FULL - (unsigned)i));

    float e2 = expf(k0);
    float* base = g_sums + (size_t)seg * REC;

    const float4* dv = (const float4*)(dense + (size_t)i * 64);
#pragma unroll
    for (int k = 0; k < 16; k++) {
        float4 v = dv[k];
        red4(base + 4 * k, v.x * e2, v.y * e2, v.z * e2, v.w * e2);
    }
    const float4* iv = (const float4*)(inst + (size_t)i * 16);
#pragma unroll
    for (int k = 0; k < 4; k++) {
        float4 v = iv[k];
        red4(base + 64 + 4 * k, v.x * e2, v.y * e2, v.z * e2, v.w * e2);
    }
    const float4* mv = (const float4*)(mot + (size_t)i * 8);
#pragma unroll
    for (int k = 0; k < 2; k++) {
        float4 v = mv[k];
        red4(base + 80 + 4 * k, v.x * e2, v.y * e2, v.z * e2, v.w * e2);
    }
    {
        float4 v = ((const float4*)(rot + (size_t)i * 4))[0];
        red4(base + 88, v.x * e2, v.y * e2, v.z * e2, v.w * e2);
    }
    float c0 = cen[3 * (size_t)i], c1 = cen[3 * (size_t)i + 1], c2 = cen[3 * (size_t)i + 2];
    float o0 = off[3 * (size_t)i], o1 = off[3 * (size_t)i + 1], o2 = off[3 * (size_t)i + 2];
    float op = opa[i];
    float s0 = sca[3 * (size_t)i], s1 = sca[3 * (size_t)i + 1], s2 = sca[3 * (size_t)i + 2];
    float f0 = fdc[3 * (size_t)i], f1 = fdc[3 * (size_t)i + 1], f2 = fdc[3 * (size_t)i + 2];
    float dn = dyn[i];
    red4(base + 92,  c0 * e2, c1 * e2, c2 * e2, o0 * e2);
    red4(base + 96,  o1 * e2, o2 * e2, op * e2, s0 * e2);
    red4(base + 100, s1 * e2, s2 * e2, f0 * e2, f1 * e2);
    red4(base + 104, f2 * e2, dn * e2, e2,      0.0f);
}

// ---------------- Pass 3: block-staged coalesced output ----------------
__global__ __launch_bounds__(256) void k_out(
        const float* __restrict__ dense, const float* __restrict__ cen,
        const float* __restrict__ off,   const float* __restrict__ opa,
        const float* __restrict__ sca,   const float* __restrict__ rot,
        const float* __restrict__ fdc,   const float* __restrict__ kp,
        const float* __restrict__ inst,  const float* __restrict__ mot,
        const float* __restrict__ dyn,   const int* __restrict__ ids,
        float* __restrict__ out) {
    __shared__ __align__(16) float rec[NE][REC];
    __shared__ int   sact[NE];
    __shared__ int   sseg[NE];
    __shared__ float sinv[NE], sfac[NE], smx2[NE];

    int base = blockIdx.x * NE;
    int t = threadIdx.x;

    if (t < NE) {
        int i = base + t;
        int a = __ldg(&g_act[i]);
        sact[t] = a;
        sseg[t] = a ? (i / VHW) * MAXID + __ldg(&ids[i]) : 0;
    }
    __syncthreads();

    // stage records (coalesced float4 reads from L2)
#pragma unroll
    for (int it = 0; it < 8; it++) {
        int j = it * 256 + t;
        int e = j >> 5, q = j & 31;
        if (q < 28 && sact[e])
            ((float4*)rec[e])[q] =
                __ldg((const float4*)(g_sums + (size_t)sseg[e] * REC) + q);
    }
    __syncthreads();

    if (t < NE) {
        if (sact[t]) {
            sinv[t] = 1.0f / rec[t][106];
            unsigned long long pk = __ldg(&g_rep[sseg[t]]);
            unsigned ou = (unsigned)(pk >> 32);
            smx2[t] = (ou & 0x80000000u) ? __uint_as_float(ou & 0x7FFFFFFFu)
                                         : __uint_as_float(~ou);
            unsigned rep_i = FULL - (unsigned)(pk & FULL);
            sfac[t] = ((unsigned)(base + t) == rep_i) ? 1.0f : DUPF;
        } else {
            sinv[t] = 0.f; sfac[t] = 0.f; smx2[t] = 0.f;
        }
    }
    __syncthreads();

    const size_t M = M_ELEMS;
    float* o_dense = out;
    float* o_cen   = out + 64 * M;
    float* o_off   = out + 67 * M;
    float* o_opa   = out + 70 * M;
    float* o_sca   = out + 71 * M;
    float* o_rot   = out + 74 * M;
    float* o_fdc   = out + 78 * M;
    float* o_kp    = out + 81 * M;
    float* o_inst  = out + 82 * M;
    float* o_mot   = out + 98 * M;
    float* o_dyn   = out + 106 * M;

    // dense: NE*16 = 1024 float4 writes, fully coalesced
    {
        const float4* in4 = (const float4*)dense;
        float4* out4 = (float4*)o_dense;
#pragma unroll
        for (int it = 0; it < 4; it++) {
            int j = it * 256 + t;
            int e = j >> 4, q = j & 15;
            size_t g = (size_t)base * 16 + j;
            float4 v;
            if (sact[e]) {
                float iv = sinv[e];
                float4 r = ((const float4*)rec[e])[q];
                v = make_float4(r.x * iv, r.y * iv, r.z * iv, r.w * iv);
            } else {
                v = __ldg(in4 + g);
            }
            out4[g] = v;
        }
    }
    // inst: NE*4 = 256 float4
    {
        int e = t >> 2, q = t & 3;
        size_t g = (size_t)base * 4 + t;
        float4 v;
        if (sact[e]) {
            float iv = sinv[e];
            float4 r = ((const float4*)rec[e])[16 + q];
            v = make_float4(r.x * iv, r.y * iv, r.z * iv, r.w * iv);
        } else {
            v = __ldg((const float4*)inst + g);
        }
        ((float4*)o_inst)[g] = v;
    }
    // motion: NE*2 = 128 float4
    if (t < 128) {
        int e = t >> 1, q = t & 1;
        size_t g = (size_t)base * 2 + t;
        float4 v;
        if (sact[e]) {
            float iv = sinv[e];
            float4 r = ((const float4*)rec[e])[20 + q];
            v = make_float4(r.x * iv, r.y * iv, r.z * iv, r.w * iv);
        } else {
            v = __ldg((const float4*)mot + g);
        }
        ((float4*)o_mot)[g] = v;
    }
    // rotation: NE float4 (divide + normalize)
    if (t < NE) {
        size_t g = (size_t)base + t;
        float4 v;
        if (sact[t]) {
            float iv = sinv[t];
            float4 r = ((const float4*)rec[t])[22];
            v = make_float4(r.x * iv, r.y * iv, r.z * iv, r.w * iv);
            float n = sqrtf(v.x * v.x + v.y * v.y + v.z * v.z + v.w * v.w);
            float qi = 1.0f / fmaxf(n, 1e-12f);
            v = make_float4(v.x * qi, v.y * qi, v.z * qi, v.w * qi);
        } else {
            v = __ldg((const float4*)rot + g);
        }
        ((float4*)o_rot)[g] = v;
    }
    // center / offset / scale / feat_dc: NE*3 scalars each, coalesced
    if (t < NE * 3) {
        int e = t / 3, c = t - 3 * e;
        size_t g = (size_t)base * 3 + t;
        o_cen[g] = sact[e] ? rec[e][92 + c] * sinv[e] : __ldg(cen + g);
        o_off[g] = sact[e] ? rec[e][95 + c] * sinv[e] : __ldg(off + g);
        o_sca[g] = sact[e] ? rec[e][99 + c] * sinv[e] : __ldg(sca + g);
        o_fdc[g] = sact[e] ? rec[e][102 + c] * sinv[e] : __ldg(fdc + g);
    }
    // opacity / keep / dynamic: NE scalars each
    if (t < NE) {
        size_t g = (size_t)base + t;
        if (sact[t]) {
            o_opa[g] = rec[t][98] * sinv[t] * sfac[t];
            o_kp[g]  = smx2[t] * sfac[t];
            o_dyn[g] = rec[t][105] * sinv[t];
        } else {
            o_opa[g] = __ldg(opa + g);
            o_kp[g]  = __ldg(kp + g);
            o_dyn[g] = __ldg(dyn + g);
        }
    }
}

extern "C" void kernel_launch(void* const* d_in, const int* in_sizes, int n_in,
                              void* d_out, int out_size) {
    const float* dense = (const float*)d_in[0];
    const float* cen   = (const float*)d_in[1];
    const float* off   = (const float*)d_in[2];
    const float* opa   = (const float*)d_in[3];
    const float* sca   = (const float*)d_in[4];
    const float* rot   = (const float*)d_in[5];
    const float* fdc   = (const float*)d_in[6];
    const float* kp    = (const float*)d_in[7];
    const float* inst  = (const float*)d_in[8];
    const float* mot   = (const float*)d_in[9];
    const float* dyn   = (const float*)d_in[10];
    const int*   ids   = (const int*)d_in[11];
    float* out = (float*)d_out;

    // zero scratch via DMA memsets (all-zero patterns are valid initials)
    void *p_cnt, *p_e1c, *p_rep, *p_sums;
    cudaGetSymbolAddress(&p_cnt,  g_cnt);
    cudaGetSymbolAddress(&p_e1c,  g_e1c);
    cudaGetSymbolAddress(&p_rep,  g_rep);
    cudaGetSymbolAddress(&p_sums, g_sums);
    cudaMemsetAsync(p_cnt,  0, sizeof(int) * NSEGS);
    cudaMemsetAsync(p_e1c,  0, sizeof(float4) * NSEGS);
    cudaMemsetAsync(p_rep,  0, sizeof(unsigned long long) * NSEGS);
    cudaMemsetAsync(p_sums, 0, sizeof(float) * (size_t)NSEGS * REC);

    const int TB = 256;
    const int gM = (M_ELEMS + TB - 1) / TB;
    const int g4 = (M_ELEMS / 4 + TB - 1) / TB;
    const int gO = M_ELEMS / NE;

    k_p12<<<g4, TB>>>(ids, kp, cen);
    k_p34<<<gM, TB>>>(dense, cen, off, opa, sca, rot, fdc, kp, inst, mot, dyn, ids);
    k_out<<<gO, TB>>>(dense, cen, off, opa, sca, rot, fdc, kp, inst, mot, dyn, ids, out);
}

// round 6
// speedup vs baseline: 1.6877x; 1.0160x over previous
#include <cuda_runtime.h>

// Fixed problem shape: B=1, T=4, V=6, H=128, W=128
#define MAXID    8192
#define BT       4
#define M_ELEMS  393216
#define VHW      (M_ELEMS / BT)       // 98304
#define NSEGS    (BT * MAXID)         // 32768
#define REC      112                  // per-segment record (floats), 448B
#define THRF     2.0f
#define DUPF     0.05f
#define FULL     0xffffffffu
#define NE       64                   // elements per k_out block

// Record layout (float slots):
//  [0..63] dense  [64..79] inst  [80..87] motion  [88..91] rot
//  [92..94] center [95..97] offset [98] opacity [99..101] scale
//  [102..104] feat_dc [105] dyn [106] d2 (sum e2) [107..111] pad

__device__ int                g_cnt[NSEGS];
__device__ float4             g_e1c[NSEGS];   // {d1, sum(cen*e1).xyz}
__device__ unsigned long long g_rep[NSEGS];   // packed (ordered(k)<<32 | ~i)
__device__ unsigned char      g_act[M_ELEMS];
__device__ __align__(16) float g_sums[(size_t)NSEGS * REC];

__device__ __forceinline__ void red4(float* addr, float a, float b, float c, float d) {
    asm volatile("red.global.add.v4.f32 [%0], {%1,%2,%3,%4};"
                 :: "l"(addr), "f"(a), "f"(b), "f"(c), "f"(d) : "memory");
}

// ---------------- Pass 1: count + e1/cen*e1 accumulate (4 elems/thread) ----
__global__ void k_p12(const int* __restrict__ ids, const float* __restrict__ kp,
                      const float* __restrict__ cen) {
    int base = (blockIdx.x * blockDim.x + threadIdx.x) * 4;
    if (base >= M_ELEMS) return;
    int4   id4 = *(const int4*)(ids + base);
    float4 k4  = *(const float4*)(kp + base);
    float4 c0 = *(const float4*)(cen + (size_t)base * 3);
    float4 c1 = *(const float4*)(cen + (size_t)base * 3 + 4);
    float4 c2 = *(const float4*)(cen + (size_t)base * 3 + 8);
    int bt = base / VHW;   // VHW % 4 == 0, no straddle

    int   idv[4] = {id4.x, id4.y, id4.z, id4.w};
    float kv[4]  = {k4.x, k4.y, k4.z, k4.w};
    float cx[4] = {c0.x, c0.w, c1.z, c2.y};
    float cy[4] = {c0.y, c1.x, c1.w, c2.z};
    float cz[4] = {c0.z, c1.y, c2.x, c2.w};
#pragma unroll
    for (int j = 0; j < 4; j++) {
        if (idv[j] >= 0) {
            int seg = bt * MAXID + idv[j];
            float e1 = expf(kv[j]);
            atomicAdd(&g_cnt[seg], 1);
            red4((float*)&g_e1c[seg], e1, cx[j] * e1, cy[j] * e1, cz[j] * e1);
        }
    }
}

// ------- Pass 2 (fused): act + rep + warp-cooperative weighted accumulate --
__global__ void k_p34(const float* __restrict__ dense, const float* __restrict__ cen,
                      const float* __restrict__ off,   const float* __restrict__ opa,
                      const float* __restrict__ sca,   const float* __restrict__ rot,
                      const float* __restrict__ fdc,   const float* __restrict__ kp,
                      const float* __restrict__ inst,  const float* __restrict__ mot,
                      const float* __restrict__ dyn,   const int* __restrict__ ids) {
    int i = blockIdx.x * blockDim.x + threadIdx.x;   // grid sized exactly M/32 warps
    int lane = threadIdx.x & 31;
    int i0 = i - lane;                                // warp's first element

    // ---- phase 1: per-lane activity / weight / small channels ----
    int id = ids[i];
    bool act = false;
    int seg = 0;
    float k0 = 0.f, e2 = 0.f;
    if (id >= 0) {
        seg = (i / VHW) * MAXID + id;
        if (__ldg(&g_cnt[seg]) >= 2) {
            float4 f = __ldg(&g_e1c[seg]);
            float inv = (f.x > 0.0f) ? (1.0f / f.x) : 1.0f;
            float dx = cen[3 * (size_t)i + 0] - f.y * inv;
            float dy = cen[3 * (size_t)i + 1] - f.z * inv;
            float dz = cen[3 * (size_t)i + 2] - f.w * inv;
            float dist = sqrtf(dx * dx + dy * dy + dz * dz);
            if (dist <= THRF) { act = true; k0 = kp[i]; }
        }
    }
    g_act[i] = act ? 1 : 0;

    if (act) {
        // representative: max keep_score, tie -> min index (packed 64-bit max)
        unsigned kb  = __float_as_uint(k0);
        unsigned ord = (k0 >= 0.0f) ? (kb | 0x80000000u) : ~kb;
        atomicMax(&g_rep[seg], ((unsigned long long)ord << 32) | (FULL - (unsigned)i));

        e2 = expf(k0);
        float* base = g_sums + (size_t)seg * REC;
        float c0 = cen[3 * (size_t)i], c1 = cen[3 * (size_t)i + 1], c2 = cen[3 * (size_t)i + 2];
        float o0 = off[3 * (size_t)i], o1 = off[3 * (size_t)i + 1], o2 = off[3 * (size_t)i + 2];
        float op = opa[i];
        float s0 = sca[3 * (size_t)i], s1 = sca[3 * (size_t)i + 1], s2 = sca[3 * (size_t)i + 2];
        float f0 = fdc[3 * (size_t)i], f1 = fdc[3 * (size_t)i + 1], f2 = fdc[3 * (size_t)i + 2];
        float dn = dyn[i];
        red4(base + 92,  c0 * e2, c1 * e2, c2 * e2, o0 * e2);
        red4(base + 96,  o1 * e2, o2 * e2, op * e2, s0 * e2);
        red4(base + 100, s1 * e2, s2 * e2, f0 * e2, f1 * e2);
        red4(base + 104, f2 * e2, dn * e2, e2,      0.0f);
    }

    // ---- phase 2: warp-cooperative coalesced accumulate of big channels ----
    unsigned m = __ballot_sync(FULL, act);
#pragma unroll 4
    for (int j = 0; j < 32; j++) {
        if (!((m >> j) & 1)) continue;               // uniform branch
        int   e  = i0 + j;
        int   sg = __shfl_sync(FULL, seg, j);
        float w  = __shfl_sync(FULL, e2, j);
        float4 v = make_float4(0.f, 0.f, 0.f, 0.f);
        if (lane < 16)      v = __ldg((const float4*)(dense + (size_t)e * 64) + lane);
        else if (lane < 20) v = __ldg((const float4*)(inst + (size_t)e * 16) + (lane - 16));
        else if (lane < 22) v = __ldg((const float4*)(mot + (size_t)e * 8) + (lane - 20));
        else if (lane == 22) v = __ldg((const float4*)(rot + (size_t)e * 4));
        if (lane < 23)
            red4(g_sums + (size_t)sg * REC + lane * 4,
                 v.x * w, v.y * w, v.z * w, v.w * w);
    }
}

// ---------------- Pass 3: block-staged coalesced output ----------------
__global__ __launch_bounds__(256) void k_out(
        const float* __restrict__ dense, const float* __restrict__ cen,
        const float* __restrict__ off,   const float* __restrict__ opa,
        const float* __restrict__ sca,   const float* __restrict__ rot,
        const float* __restrict__ fdc,   const float* __restrict__ kp,
        const float* __restrict__ inst,  const float* __restrict__ mot,
        const float* __restrict__ dyn,   const int* __restrict__ ids,
        float* __restrict__ out) {
    __shared__ __align__(16) float rec[NE][REC];
    __shared__ int   sact[NE];
    __shared__ int   sseg[NE];
    __shared__ float sinv[NE], sfac[NE], smx2[NE];

    int base = blockIdx.x * NE;
    int t = threadIdx.x;

    if (t < NE) {
        int i = base + t;
        int a = __ldg(&g_act[i]);
        sact[t] = a;
        sseg[t] = a ? (i / VHW) * MAXID + __ldg(&ids[i]) : 0;
    }
    __syncthreads();

    // stage records (coalesced float4 reads from L2)
#pragma unroll
    for (int it = 0; it < 8; it++) {
        int j = it * 256 + t;
        int e = j >> 5, q = j & 31;
        if (q < 28 && sact[e])
            ((float4*)rec[e])[q] =
                __ldg((const float4*)(g_sums + (size_t)sseg[e] * REC) + q);
    }
    __syncthreads();

    if (t < NE) {
        if (sact[t]) {
            sinv[t] = 1.0f / rec[t][106];
            unsigned long long pk = __ldg(&g_rep[sseg[t]]);
            unsigned ou = (unsigned)(pk >> 32);
            smx2[t] = (ou & 0x80000000u) ? __uint_as_float(ou & 0x7FFFFFFFu)
                                         : __uint_as_float(~ou);
            unsigned rep_i = FULL - (unsigned)(pk & FULL);
            sfac[t] = ((unsigned)(base + t) == rep_i) ? 1.0f : DUPF;
        } else {
            sinv[t] = 0.f; sfac[t] = 0.f; smx2[t] = 0.f;
        }
    }
    __syncthreads();

    const size_t M = M_ELEMS;
    float* o_dense = out;
    float* o_cen   = out + 64 * M;
    float* o_off   = out + 67 * M;
    float* o_opa   = out + 70 * M;
    float* o_sca   = out + 71 * M;
    float* o_rot   = out + 74 * M;
    float* o_fdc   = out + 78 * M;
    float* o_kp    = out + 81 * M;
    float* o_inst  = out + 82 * M;
    float* o_mot   = out + 98 * M;
    float* o_dyn   = out + 106 * M;

    // dense: NE*16 = 1024 float4 writes, fully coalesced
    {
        const float4* in4 = (const float4*)dense;
        float4* out4 = (float4*)o_dense;
#pragma unroll
        for (int it = 0; it < 4; it++) {
            int j = it * 256 + t;
            int e = j >> 4, q = j & 15;
            size_t g = (size_t)base * 16 + j;
            float4 v;
            if (sact[e]) {
                float iv = sinv[e];
                float4 r = ((const float4*)rec[e])[q];
                v = make_float4(r.x * iv, r.y * iv, r.z * iv, r.w * iv);
            } else {
                v = __ldg(in4 + g);
            }
            out4[g] = v;
        }
    }
    // inst: NE*4 = 256 float4
    {
        int e = t >> 2, q = t & 3;
        size_t g = (size_t)base * 4 + t;
        float4 v;
        if (sact[e]) {
            float iv = sinv[e];
            float4 r = ((const float4*)rec[e])[16 + q];
            v = make_float4(r.x * iv, r.y * iv, r.z * iv, r.w * iv);
        } else {
            v = __ldg((const float4*)inst + g);
        }
        ((float4*)o_inst)[g] = v;
    }
    // motion: NE*2 = 128 float4
    if (t < 128) {
        int e = t >> 1, q = t & 1;
        size_t g = (size_t)base * 2 + t;
        float4 v;
        if (sact[e]) {
            float iv = sinv[e];
            float4 r = ((const float4*)rec[e])[20 + q];
            v = make_float4(r.x * iv, r.y * iv, r.z * iv, r.w * iv);
        } else {
            v = __ldg((const float4*)mot + g);
        }
        ((float4*)o_mot)[g] = v;
    }
    // rotation: NE float4 (divide + normalize)
    if (t < NE) {
        size_t g = (size_t)base + t;
        float4 v;
        if (sact[t]) {
            float iv = sinv[t];
            float4 r = ((const float4*)rec[t])[22];
            v = make_float4(r.x * iv, r.y * iv, r.z * iv, r.w * iv);
            float n = sqrtf(v.x * v.x + v.y * v.y + v.z * v.z + v.w * v.w);
            float qi = 1.0f / fmaxf(n, 1e-12f);
            v = make_float4(v.x * qi, v.y * qi, v.z * qi, v.w * qi);
        } else {
            v = __ldg((const float4*)rot + g);
        }
        ((float4*)o_rot)[g] = v;
    }
    // center / offset / scale / feat_dc: NE*3 scalars each, coalesced
    if (t < NE * 3) {
        int e = t / 3, c = t - 3 * e;
        size_t g = (size_t)base * 3 + t;
        o_cen[g] = sact[e] ? rec[e][92 + c] * sinv[e] : __ldg(cen + g);
        o_off[g] = sact[e] ? rec[e][95 + c] * sinv[e] : __ldg(off + g);
        o_sca[g] = sact[e] ? rec[e][99 + c] * sinv[e] : __ldg(sca + g);
        o_fdc[g] = sact[e] ? rec[e][102 + c] * sinv[e] : __ldg(fdc + g);
    }
    // opacity / keep / dynamic: NE scalars each
    if (t < NE) {
        size_t g = (size_t)base + t;
        if (sact[t]) {
            o_opa[g] = rec[t][98] * sinv[t] * sfac[t];
            o_kp[g]  = smx2[t] * sfac[t];
            o_dyn[g] = rec[t][105] * sinv[t];
        } else {
            o_opa[g] = __ldg(opa + g);
            o_kp[g]  = __ldg(kp + g);
            o_dyn[g] = __ldg(dyn + g);
        }
    }
}

extern "C" void kernel_launch(void* const* d_in, const int* in_sizes, int n_in,
                              void* d_out, int out_size) {
    const float* dense = (const float*)d_in[0];
    const float* cen   = (const float*)d_in[1];
    const float* off   = (const float*)d_in[2];
    const float* opa   = (const float*)d_in[3];
    const float* sca   = (const float*)d_in[4];
    const float* rot   = (const float*)d_in[5];
    const float* fdc   = (const float*)d_in[6];
    const float* kp    = (const float*)d_in[7];
    const float* inst  = (const float*)d_in[8];
    const float* mot   = (const float*)d_in[9];
    const float* dyn   = (const float*)d_in[10];
    const int*   ids   = (const int*)d_in[11];
    float* out = (float*)d_out;

    // zero scratch via DMA memsets (all-zero patterns are valid initials)
    void *p_cnt, *p_e1c, *p_rep, *p_sums;
    cudaGetSymbolAddress(&p_cnt,  g_cnt);
    cudaGetSymbolAddress(&p_e1c,  g_e1c);
    cudaGetSymbolAddress(&p_rep,  g_rep);
    cudaGetSymbolAddress(&p_sums, g_sums);
    cudaMemsetAsync(p_cnt,  0, sizeof(int) * NSEGS);
    cudaMemsetAsync(p_e1c,  0, sizeof(float4) * NSEGS);
    cudaMemsetAsync(p_rep,  0, sizeof(unsigned long long) * NSEGS);
    cudaMemsetAsync(p_sums, 0, sizeof(float) * (size_t)NSEGS * REC);

    const int TB = 256;
    const int gM = (M_ELEMS + TB - 1) / TB;
    const int g4 = (M_ELEMS / 4 + TB - 1) / TB;
    const int gO = M_ELEMS / NE;

    k_p12<<<g4, TB>>>(ids, kp, cen);
    k_p34<<<gM, TB>>>(dense, cen, off, opa, sca, rot, fdc, kp, inst, mot, dyn, ids);
    k_out<<<gO, TB>>>(dense, cen, off, opa, sca, rot, fdc, kp, inst, mot, dyn, ids, out);
}